// round 1
// baseline (speedup 1.0000x reference)
#include <cuda_runtime.h>

#define NEGC (-10000.0f)
#define NB 32
#define NS 256
#define ND 512
#define NK 8
#define NL 64
#define NJ 36   // number of (k,h) pairs, h <= k

// Scratch (static device allocations are allowed)
__device__ float g_effw[(size_t)NJ * NL * ND];   // 4.7 MB
__device__ float g_effb[NK * NL];
__device__ float g_ls[(size_t)NB * NS * NK * NL]; // 16.8 MB, layout [b][s][k][l]
__device__ float g_M[(size_t)NB * NS * NL];       // 2 MB, layout [b][t][l]

// ---------------------------------------------------------------------------
// Kernel A: eff_w[(k,h)][l][i] = sum_o cls_w[l][o] * conv_w[k][o][i][h]
// grid: (36, 8)  block: 256.  Output tile: 64 l x 64 i per block.
// ---------------------------------------------------------------------------
__global__ void __launch_bounds__(256) eff_kernel(const float* __restrict__ conv_w,
                                                  const float* __restrict__ cls_w) {
    int j = blockIdx.x;
    int k = 0, rem = j;
    while (rem > k) { rem -= (k + 1); k++; }
    int h = rem;
    int i0 = blockIdx.y * 64;

    __shared__ float As[32][65];   // [o][i]
    __shared__ float Bs[64][33];   // [l][o]

    int tid = threadIdx.x;
    int lx = tid & 15;   // i fast
    int ly = tid >> 4;   // l
    float acc[4][4] = {};

    for (int o0 = 0; o0 < ND; o0 += 32) {
        for (int idx = tid; idx < 32 * 64; idx += 256) {
            int o = idx >> 6, i = idx & 63;
            As[o][i] = conv_w[(((size_t)k * ND + (o0 + o)) * ND + (i0 + i)) * NK + h];
        }
        for (int idx = tid; idx < 64 * 32; idx += 256) {
            int l = idx >> 5, o = idx & 31;
            Bs[l][o] = cls_w[l * ND + o0 + o];
        }
        __syncthreads();
#pragma unroll
        for (int o = 0; o < 32; o++) {
            float a[4], bb[4];
#pragma unroll
            for (int u = 0; u < 4; u++) a[u] = As[o][lx + 16 * u];
#pragma unroll
            for (int u = 0; u < 4; u++) bb[u] = Bs[ly + 16 * u][o];
#pragma unroll
            for (int y = 0; y < 4; y++)
#pragma unroll
                for (int x = 0; x < 4; x++) acc[y][x] += a[x] * bb[y];
        }
        __syncthreads();
    }
#pragma unroll
    for (int y = 0; y < 4; y++) {
        int l = ly + 16 * y;
#pragma unroll
        for (int x = 0; x < 4; x++) {
            int i = i0 + lx + 16 * x;
            g_effw[((size_t)j * NL + l) * ND + i] = acc[y][x];
        }
    }
}

// eff_b[k][l] = sum_o cls_w[l][o]*conv_b[k][o] + cls_b[l]
__global__ void effb_kernel(const float* __restrict__ cls_w,
                            const float* __restrict__ conv_b,
                            const float* __restrict__ cls_b) {
    int tid = threadIdx.x;
    int k = tid >> 6, l = tid & 63;
    float s = 0.f;
    for (int o = 0; o < ND; o++) s += cls_w[l * ND + o] * conv_b[k * ND + o];
    g_effb[k * NL + l] = s + cls_b[l];
}

// ---------------------------------------------------------------------------
// Kernel B: label_score[b][s][k][l] = sum_{h<=k} sum_d wr[b][s-k+h][d]*eff_w[(k,h)][l][d]
//           + eff_b[k][l]; with PAD/mask/seg_ok -> NEG baked in.
// grid: (B*4, K)  block: 256.  64 s-positions x 64 l per block.
// ---------------------------------------------------------------------------
__global__ void __launch_bounds__(256) ls_kernel(const float* __restrict__ wr,
                                                 const int* __restrict__ mask) {
    int k = blockIdx.y;
    int bx = blockIdx.x;
    int b = bx >> 2;
    int s0 = (bx & 3) * 64;

    __shared__ float wrs[72][65];  // rows s0-7 .. s0+63 (clamped), one 64-wide d chunk
    __shared__ float Es[64][65];   // eff_w chunk [l][d]

    int tid = threadIdx.x;
    int lx = tid & 15;   // l fast (coalesced stores)
    int sy = tid >> 4;   // s
    float acc[4][4] = {};  // [si][li]: s = s0+sy+16si, l = lx+16li

    const float* wrb = wr + (size_t)b * NS * ND;

    for (int dc = 0; dc < ND; dc += 64) {
        __syncthreads();
        for (int idx = tid; idx < 71 * 64; idx += 256) {
            int rr = idx >> 6, d = idx & 63;
            int r = s0 - 7 + rr;
            r = r < 0 ? 0 : r;
            wrs[rr][d] = wrb[(size_t)r * ND + dc + d];
        }
        for (int h = 0; h <= k; h++) {
            int j = k * (k + 1) / 2 + h;
            __syncthreads();
            for (int idx = tid; idx < 4096; idx += 256) {
                int l = idx >> 6, d = idx & 63;
                Es[l][d] = g_effw[((size_t)j * NL + l) * ND + dc + d];
            }
            __syncthreads();
            int roff = 7 - k + h;
#pragma unroll 4
            for (int d = 0; d < 64; d++) {
                float bb[4], a[4];
#pragma unroll
                for (int u = 0; u < 4; u++) bb[u] = Es[lx + 16 * u][d];
#pragma unroll
                for (int si = 0; si < 4; si++) a[si] = wrs[sy + 16 * si + roff][d];
#pragma unroll
                for (int si = 0; si < 4; si++)
#pragma unroll
                    for (int u = 0; u < 4; u++) acc[si][u] += a[si] * bb[u];
            }
        }
    }

    // epilogue: add bias, apply NEG masking, store
#pragma unroll
    for (int si = 0; si < 4; si++) {
        int s = s0 + sy + 16 * si;
        int mv = mask[b * NS + s];
        bool ok = (mv == 1) && (k <= s);
#pragma unroll
        for (int u = 0; u < 4; u++) {
            int l = lx + 16 * u;
            float v = acc[si][u] + g_effb[k * NL + l];
            if (l == 0 || !ok) v = NEGC;
            g_ls[(((size_t)b * NS + s) * NK + k) * NL + l] = v;
        }
    }
}

// ---------------------------------------------------------------------------
// Kernel C: semi-CRF forward DP + finalization. One block per batch element.
// ---------------------------------------------------------------------------
__global__ void __launch_bounds__(256) dp_kernel(const int* __restrict__ mask,
                                                 const float* __restrict__ T,
                                                 const float* __restrict__ TFB,
                                                 const float* __restrict__ TTE,
                                                 float* __restrict__ out) {
    int b = blockIdx.x;
    int tid = threadIdx.x;
    int lane = tid & 31;
    int warp = tid >> 5;
    int l = tid >> 2;   // 0..63
    int q = tid & 3;    // 0..3, handles k=q and k=q+4

    __shared__ float sExpT[64 * 65];
    __shared__ float sMring[16 * 65];
    __shared__ __align__(16) float sLs[4][512];
    __shared__ float sExpA[64];
    __shared__ float sA[64];
    __shared__ float sMaxA;
    __shared__ float sTFB[64], sTTE[64];
    __shared__ float sRed[8];
    __shared__ int sLen;

    if (tid < 64) { sTFB[tid] = TFB[tid]; sTTE[tid] = TTE[tid]; }
    for (int idx = tid; idx < 4096; idx += 256)
        sExpT[(idx >> 6) * 65 + (idx & 63)] = __expf(T[idx]);
    if (tid == 0) sLen = 0;

    const float* lsb = g_ls + (size_t)b * NS * NK * NL;
    const int* mb = mask + b * NS;

    unsigned sls_base = (unsigned)__cvta_generic_to_shared(&sLs[0][0]);
    // prefetch stages 0..2
    for (int p = 0; p < 3; p++) {
        unsigned dst = sls_base + (unsigned)((p * 512 + tid * 2) * 4);
        const float* src = lsb + p * 512 + tid * 2;
        asm volatile("cp.async.ca.shared.global [%0], [%1], 8;" :: "r"(dst), "l"(src));
        asm volatile("cp.async.commit_group;");
    }
    __syncthreads();

    for (int t = 0; t < NS; t++) {
        // prefetch ls for step t+3
        if (t + 3 < NS) {
            unsigned dst = sls_base + (unsigned)((((t + 3) & 3) * 512 + tid * 2) * 4);
            const float* src = lsb + (t + 3) * 512 + tid * 2;
            asm volatile("cp.async.ca.shared.global [%0], [%1], 8;" :: "r"(dst), "l"(src));
        }
        asm volatile("cp.async.commit_group;");

        if (t > 0) {
            // M[t-1][l] = log( sum_l' expT[l][l'] * expA[l'] ) + maxA
            float p = 0.f;
            const float* rowT = &sExpT[l * 65 + q * 16];
            const float* ea = &sExpA[q * 16];
#pragma unroll
            for (int jj = 0; jj < 16; jj++) p += rowT[jj] * ea[jj];
            p += __shfl_xor_sync(0xffffffffu, p, 1);
            p += __shfl_xor_sync(0xffffffffu, p, 2);
            if (q == 0) {
                float m = __logf(p) + sMaxA;
                m = fmaxf(m, -1e30f);  // kill -inf on dead PAD lane
                sMring[((t - 1) & 15) * 65 + l] = m;
                g_M[((size_t)b * NS + (t - 1)) * NL + l] = m;
            }
        }
        asm volatile("cp.async.wait_group 3;" ::: "memory");
        __syncthreads();

        // A[t][l] = LSE_k of row values
        int mv = mb[t];
        const float* lst = &sLs[t & 3][0];
        float v[2];
#pragma unroll
        for (int u = 0; u < 2; u++) {
            int k = q + 4 * u;
            float lsv = lst[k * 64 + l];
            if (k == t)      v[u] = lsv + sTFB[l];
            else if (k > t)  v[u] = NEGC;
            else             v[u] = (mv == 1) ? lsv + sMring[((t - 1 - k) & 15) * 65 + l] : NEGC;
        }
        float mx = fmaxf(v[0], v[1]);
        mx = fmaxf(mx, __shfl_xor_sync(0xffffffffu, mx, 1));
        mx = fmaxf(mx, __shfl_xor_sync(0xffffffffu, mx, 2));
        float sm = __expf(v[0] - mx) + __expf(v[1] - mx);
        sm += __shfl_xor_sync(0xffffffffu, sm, 1);
        sm += __shfl_xor_sync(0xffffffffu, sm, 2);
        if (q == 0) sA[l] = __logf(sm) + mx;
        __syncthreads();

        if (warp == 0) {
            float a0 = sA[lane], a1 = sA[lane + 32];
            float m2 = fmaxf(a0, a1);
#pragma unroll
            for (int o = 16; o > 0; o >>= 1)
                m2 = fmaxf(m2, __shfl_xor_sync(0xffffffffu, m2, o));
            sExpA[lane]      = __expf(a0 - m2);
            sExpA[lane + 32] = __expf(a1 - m2);
            if (lane == 0) sMaxA = m2;
        }
        __syncthreads();
    }

    // lengths[b] = sum mask
    {
        int mv = mb[tid];
#pragma unroll
        for (int o = 16; o > 0; o >>= 1) mv += __shfl_xor_sync(0xffffffffu, mv, o);
        if (lane == 0) atomicAdd(&sLen, mv);
    }
    __syncthreads();
    int len = sLen;

    // final scores[k][l] = row(t_idx)[k][l] + T_to_END[l]
    float vv[2];
#pragma unroll
    for (int u = 0; u < 2; u++) {
        int k = q + 4 * u;
        int tk = len - 1 - k;
        int tix = (tk >= 0) ? tk : (NS - 1);
        float lsv = lsb[(size_t)tix * (NK * NL) + k * NL + l];
        float gv;
        if (k == tix)      gv = lsv + sTFB[l];
        else if (k > tix)  gv = NEGC;
        else               gv = (mb[tix] == 1)
                                  ? lsv + g_M[((size_t)b * NS + (tix - 1 - k)) * NL + l]
                                  : NEGC;
        vv[u] = gv + sTTE[l];
    }
    // block LSE over 512 values
    float mx = fmaxf(vv[0], vv[1]);
#pragma unroll
    for (int o = 16; o > 0; o >>= 1) mx = fmaxf(mx, __shfl_xor_sync(0xffffffffu, mx, o));
    if (lane == 0) sRed[warp] = mx;
    __syncthreads();
    if (tid == 0) {
        float m = sRed[0];
#pragma unroll
        for (int w = 1; w < 8; w++) m = fmaxf(m, sRed[w]);
        sMaxA = m;
    }
    __syncthreads();
    float gm = sMaxA;
    float e = __expf(vv[0] - gm) + __expf(vv[1] - gm);
#pragma unroll
    for (int o = 16; o > 0; o >>= 1) e += __shfl_xor_sync(0xffffffffu, e, o);
    if (lane == 0) sRed[warp] = e;
    __syncthreads();
    if (tid == 0) {
        float s = 0.f;
#pragma unroll
        for (int w = 0; w < 8; w++) s += sRed[w];
        out[b] = __logf(s) + gm;
    }
}

// ---------------------------------------------------------------------------
extern "C" void kernel_launch(void* const* d_in, const int* in_sizes, int n_in,
                              void* d_out, int out_size) {
    const float* word_rep = (const float*)d_in[0];
    const int*   mask     = (const int*)  d_in[1];
    const float* conv_w   = (const float*)d_in[2];
    const float* conv_b   = (const float*)d_in[3];
    const float* cls_w    = (const float*)d_in[4];
    const float* cls_b    = (const float*)d_in[5];
    const float* T        = (const float*)d_in[6];
    const float* TFB      = (const float*)d_in[7];
    const float* TTE      = (const float*)d_in[8];
    float* out = (float*)d_out;

    eff_kernel<<<dim3(NJ, 8), 256>>>(conv_w, cls_w);
    effb_kernel<<<1, NK * NL>>>(cls_w, conv_b, cls_b);
    ls_kernel<<<dim3(NB * 4, NK), 256>>>(word_rep, mask);
    dp_kernel<<<NB, 256>>>(mask, T, TFB, TTE, out);
}